// round 14
// baseline (speedup 1.0000x reference)
#include <cuda_runtime.h>
#include <cuda_bf16.h>
#include <cuda_fp16.h>
#include <cstdint>

#define NN 50000
#define NE 1600000
#define NLAYER 4
#define BN_EPS 1e-5f

// ---------------- scratch (device globals) ----------------
__device__ __align__(16) float g_h[NN * 64];
__device__ __align__(16) float g_P[NN * 64];
__device__ __align__(16) float g_Q[NN * 64];
__device__ __align__(16) float g_aggr[NN * 64];
__device__ __align__(16) float g_zn[NN * 64];
__device__ __align__(16) float g_zn2[NN * 64];
__device__ __align__(16) __half g_z2h[(size_t)NE * 64];   // fp16 z2 edge scratch
__device__ __align__(16) float g_stats[2048];

__device__ __forceinline__ int swz(int r, int kb) {
    return r * 128 + (kb ^ ((r & 7) << 4));
}

// ---------------- helpers ----------------
__device__ __forceinline__ void bn_coef(const float* __restrict__ R,
                                        const float* __restrict__ gam,
                                        const float* __restrict__ bet,
                                        float invCnt, int c, float& sc, float& sh) {
    float mu = R[c] * invCnt;
    float var = R[64 + c] * invCnt - mu * mu;
    sc = gam[c] * rsqrtf(var + BN_EPS);
    sh = bet[c] - mu * sc;
}

__device__ __forceinline__ void mma4(float c[4], uint32_t a0, uint32_t a1, uint32_t a2,
                                     uint32_t a3, uint32_t b0, uint32_t b1) {
    asm volatile(
        "mma.sync.aligned.m16n8k16.row.col.f32.bf16.bf16.f32 "
        "{%0,%1,%2,%3}, {%4,%5,%6,%7}, {%8,%9}, {%0,%1,%2,%3};\n"
        : "+f"(c[0]), "+f"(c[1]), "+f"(c[2]), "+f"(c[3])
        : "r"(a0), "r"(a1), "r"(a2), "r"(a3), "r"(b0), "r"(b1));
}

__device__ __forceinline__ void mma4h(float c[4], uint32_t a0, uint32_t a1, uint32_t a2,
                                      uint32_t a3, uint32_t b0, uint32_t b1) {
    asm volatile(
        "mma.sync.aligned.m16n8k16.row.col.f32.f16.f16.f32 "
        "{%0,%1,%2,%3}, {%4,%5,%6,%7}, {%8,%9}, {%0,%1,%2,%3};\n"
        : "+f"(c[0]), "+f"(c[1]), "+f"(c[2]), "+f"(c[3])
        : "r"(a0), "r"(a1), "r"(a2), "r"(a3), "r"(b0), "r"(b1));
}

__device__ __forceinline__ void ldsm_x4(uint32_t& r0, uint32_t& r1, uint32_t& r2,
                                        uint32_t& r3, uint32_t addr) {
    asm volatile("ldmatrix.sync.aligned.m8n8.x4.shared.b16 {%0,%1,%2,%3}, [%4];"
                 : "=r"(r0), "=r"(r1), "=r"(r2), "=r"(r3) : "r"(addr));
}

__device__ __forceinline__ uint32_t ldsm_addr(uint32_t base, int row0, int kb, int lane) {
    int row = row0 + (lane & 15);
    int kbb = kb + (lane & 16);
    return base + row * 128 + (kbb ^ ((row & 7) << 4));
}

// C[128x64] += A[128x64] @ B[64x64]; 8 warps each m16 x n64. bf16 3-term split (node side).
__device__ __forceinline__ void mma_block(uint32_t AhS, uint32_t AlS,
                                          uint32_t BhS, uint32_t BlS,
                                          float acc[8][4], int warp, int lane) {
    int ra0 = warp * 16;
#pragma unroll
    for (int kk = 0; kk < 4; kk++) {
        int kb = kk * 32;
        uint32_t ah0, ah1, ah2, ah3, al0, al1, al2, al3;
        ldsm_x4(ah0, ah1, ah2, ah3, ldsm_addr(AhS, ra0, kb, lane));
        ldsm_x4(al0, al1, al2, al3, ldsm_addr(AlS, ra0, kb, lane));
#pragma unroll
        for (int np = 0; np < 4; np++) {
            uint32_t b00, b01, b10, b11, c00, c01, c10, c11;
            ldsm_x4(b00, b01, b10, b11, ldsm_addr(BhS, np * 16, kb, lane));
            ldsm_x4(c00, c01, c10, c11, ldsm_addr(BlS, np * 16, kb, lane));
            mma4(acc[np * 2], ah0, ah1, ah2, ah3, b00, b10);
            mma4(acc[np * 2], ah0, ah1, ah2, ah3, c00, c10);
            mma4(acc[np * 2], al0, al1, al2, al3, b00, b10);
            mma4(acc[np * 2 + 1], ah0, ah1, ah2, ah3, b01, b11);
            mma4(acc[np * 2 + 1], ah0, ah1, ah2, ah3, c01, c11);
            mma4(acc[np * 2 + 1], al0, al1, al2, al3, b01, b11);
        }
    }
}

// bf16 weight split (node side)
__device__ __forceinline__ void load_B_split(const float* __restrict__ W,
                                             uint8_t* Bh, uint8_t* Bl, int tid) {
    for (int i = tid; i < 4096; i += 256) {
        int k = i >> 6, n = i & 63;
        float w = W[i];
        __nv_bfloat16 hh = __float2bfloat16(w);
        int o = swz(n, 2 * k);
        *(__nv_bfloat16*)(Bh + o) = hh;
        *(__nv_bfloat16*)(Bl + o) = __float2bfloat16(w - __bfloat162float(hh));
    }
}

// fp16 weight split (edge z2)
__device__ __forceinline__ void load_B_split_h(const float* __restrict__ W,
                                               uint8_t* Bh, uint8_t* Bl, int tid) {
    for (int i = tid; i < 4096; i += 256) {
        int k = i >> 6, n = i & 63;
        float w = W[i];
        __half hh = __float2half_rn(w);
        int o = swz(n, 2 * k);
        *(__half*)(Bh + o) = hh;
        *(__half*)(Bl + o) = __float2half_rn(w - __half2float(hh));
    }
}

// bf16 hi/lo A split-store (node side)
__device__ __forceinline__ void splitA4(uint8_t* Ah, uint8_t* Al, int r, int c4, float4 v) {
    int o = swz(r, 2 * c4);
    float2 p0 = make_float2(v.x, v.y), p1 = make_float2(v.z, v.w);
    __nv_bfloat162 h0 = __float22bfloat162_rn(p0);
    __nv_bfloat162 h1 = __float22bfloat162_rn(p1);
    uint2 hv;
    hv.x = *(uint32_t*)&h0; hv.y = *(uint32_t*)&h1;
    *(uint2*)(Ah + o) = hv;
    float2 r0 = make_float2(p0.x - __low2float(h0), p0.y - __high2float(h0));
    float2 r1 = make_float2(p1.x - __low2float(h1), p1.y - __high2float(h1));
    __nv_bfloat162 l0 = __float22bfloat162_rn(r0);
    __nv_bfloat162 l1 = __float22bfloat162_rn(r1);
    uint2 lv;
    lv.x = *(uint32_t*)&l0; lv.y = *(uint32_t*)&l1;
    *(uint2*)(Al + o) = lv;
}

// fp16 A store (edge z2)
__device__ __forceinline__ void storeA4h(uint8_t* Ah, int r, int c4, float4 v) {
    int o = swz(r, 2 * c4);
    __half2 h0 = __floats2half2_rn(v.x, v.y);
    __half2 h1 = __floats2half2_rn(v.z, v.w);
    uint2 hv;
    hv.x = *(uint32_t*)&h0; hv.y = *(uint32_t*)&h1;
    *(uint2*)(Ah + o) = hv;
}

__device__ __forceinline__ void stats_reduce_store(float* sbuf, const float localS[16],
                                                   const float localQ[16], int lane, int tid,
                                                   float* __restrict__ Rout) {
    __syncthreads();
    for (int i = tid; i < 128; i += 256) sbuf[i] = 0.f;
    __syncthreads();
    int t = lane & 3;
#pragma unroll
    for (int n0 = 0; n0 < 8; n0++) {
        atomicAdd(sbuf + n0 * 8 + 2 * t, localS[n0 * 2]);
        atomicAdd(sbuf + n0 * 8 + 2 * t + 1, localS[n0 * 2 + 1]);
        atomicAdd(sbuf + 64 + n0 * 8 + 2 * t, localQ[n0 * 2]);
        atomicAdd(sbuf + 64 + n0 * 8 + 2 * t + 1, localQ[n0 * 2 + 1]);
    }
    __syncthreads();
    for (int i = tid; i < 128; i += 256) atomicAdd(Rout + i, sbuf[i]);
}

#define DECL_SMEM                                              \
    __shared__ __align__(16) uint8_t Ah[16384], Al[16384];     \
    __shared__ __align__(16) uint8_t Bh[8192], Bl[8192];       \
    uint32_t AhS = (uint32_t)__cvta_generic_to_shared(Ah);     \
    uint32_t AlS = (uint32_t)__cvta_generic_to_shared(Al);     \
    uint32_t BhS = (uint32_t)__cvta_generic_to_shared(Bh);     \
    uint32_t BlS = (uint32_t)__cvta_generic_to_shared(Bl);

// ---------------- kernels ----------------

__global__ void k_lin_in(const float* __restrict__ x, const float* __restrict__ W,
                         const float* __restrict__ b) {
    __shared__ __align__(16) float Ws[6 * 64];
    __shared__ float bs[64];
    int tid = threadIdx.x;
    for (int i = tid; i < 384; i += 256) Ws[i] = W[i];
    if (tid < 64) bs[tid] = b[tid];
    if (blockIdx.x == 0)
        for (int i = tid; i < 2048; i += 256) g_stats[i] = 0.f;
    __syncthreads();
    int c = tid & 63;
    for (int n = blockIdx.x * 4 + (tid >> 6); n < NN; n += gridDim.x * 4) {
        float acc = bs[c];
#pragma unroll
        for (int k = 0; k < 6; k++) acc = fmaf(x[n * 6 + k], Ws[k * 64 + c], acc);
        g_h[n * 64 + c] = acc;
    }
}

// (h += relu(bn4_{l-1}(zn2)) fused when doUpd); P = h@W1[:64]; Q = h@W1[64:128]; zero aggr
__global__ void k_node_PQ(const float* __restrict__ W1, const float* __restrict__ gam,
                          const float* __restrict__ bet, int prevRegion, int doUpd) {
    DECL_SMEM
    int tid = threadIdx.x, warp = tid >> 5, lane = tid & 31;
    int row0 = blockIdx.x * 128;
    const float* Rp = g_stats + prevRegion * 128;
    const float invN = 1.0f / (float)NN;

    for (int i = tid; i < 2048; i += 256) {
        int r = i >> 4;
        int c4 = (i & 15) * 4;
        int gr = row0 + r;
        float4 v = make_float4(0, 0, 0, 0);
        if (gr < NN) {
            size_t idx = (size_t)gr * 64 + c4;
            v = *(const float4*)(g_h + idx);
            if (doUpd) {
                float4 z = *(const float4*)(g_zn2 + idx);
                float sc, sh;
                bn_coef(Rp, gam, bet, invN, c4 + 0, sc, sh); v.x += fmaxf(fmaf(z.x, sc, sh), 0.f);
                bn_coef(Rp, gam, bet, invN, c4 + 1, sc, sh); v.y += fmaxf(fmaf(z.y, sc, sh), 0.f);
                bn_coef(Rp, gam, bet, invN, c4 + 2, sc, sh); v.z += fmaxf(fmaf(z.z, sc, sh), 0.f);
                bn_coef(Rp, gam, bet, invN, c4 + 3, sc, sh); v.w += fmaxf(fmaf(z.w, sc, sh), 0.f);
                *(float4*)(g_h + idx) = v;
            }
            *(float4*)(g_aggr + idx) = make_float4(0, 0, 0, 0);
        }
        splitA4(Ah, Al, r, c4, v);
    }
    load_B_split(W1, Bh, Bl, tid);
    __syncthreads();

    int g = lane >> 2, t = lane & 3;
    int r0 = row0 + warp * 16 + g;
    {
        float acc[8][4];
#pragma unroll
        for (int i = 0; i < 8; i++) { acc[i][0]=acc[i][1]=acc[i][2]=acc[i][3]=0.f; }
        mma_block(AhS, AlS, BhS, BlS, acc, warp, lane);
#pragma unroll
        for (int n0 = 0; n0 < 8; n0++) {
            int c = n0 * 8 + 2 * t;
            if (r0 < NN) *(float2*)(g_P + (size_t)r0 * 64 + c) = make_float2(acc[n0][0], acc[n0][1]);
            if (r0 + 8 < NN) *(float2*)(g_P + (size_t)(r0 + 8) * 64 + c) = make_float2(acc[n0][2], acc[n0][3]);
        }
    }
    __syncthreads();
    load_B_split(W1 + 4096, Bh, Bl, tid);
    __syncthreads();
    {
        float acc[8][4];
#pragma unroll
        for (int i = 0; i < 8; i++) { acc[i][0]=acc[i][1]=acc[i][2]=acc[i][3]=0.f; }
        mma_block(AhS, AlS, BhS, BlS, acc, warp, lane);
#pragma unroll
        for (int n0 = 0; n0 < 8; n0++) {
            int c = n0 * 8 + 2 * t;
            if (r0 < NN) *(float2*)(g_Q + (size_t)r0 * 64 + c) = make_float2(acc[n0][0], acc[n0][1]);
            if (r0 + 8 < NN) *(float2*)(g_Q + (size_t)(r0 + 8) * 64 + c) = make_float2(acc[n0][2], acc[n0][3]);
        }
    }
}

// edge pass 1: z1 = P[dst]+Q[src]+w1c*ea -> col sums/sumsqs (index loads pipelined)
__global__ void k_edge_z1_stats(const int* __restrict__ EI, const float* __restrict__ EA,
                                const float* __restrict__ W1, int region) {
    __shared__ __align__(16) float wc[64];
    __shared__ float rb[16 * 17];
    int tid = threadIdx.x, lane = tid & 15, slot = tid >> 4;
    if (tid < 64) wc[tid] = W1[128 * 64 + tid];
    __syncthreads();
    float4 wcv = *(const float4*)(wc + lane * 4);
    float vals[8] = {0, 0, 0, 0, 0, 0, 0, 0};
    int stride = gridDim.x * 16;
    int e = blockIdx.x * 16 + slot;
    int d = 0, s = 0;
    float ea = 0.f;
    if (e < NE) { d = EI[NE + e]; s = EI[e]; ea = EA[e]; }
    while (e < NE) {
        int en = e + stride;
        int dn = 0, sn = 0;
        float ean = 0.f;
        if (en < NE) { dn = EI[NE + en]; sn = EI[en]; ean = EA[en]; }
        float4 p = *(const float4*)(g_P + (size_t)d * 64 + lane * 4);
        float4 q = *(const float4*)(g_Q + (size_t)s * 64 + lane * 4);
        float z0 = p.x + q.x + wcv.x * ea;
        float z1 = p.y + q.y + wcv.y * ea;
        float z2 = p.z + q.z + wcv.z * ea;
        float z3 = p.w + q.w + wcv.w * ea;
        vals[0] += z0; vals[1] += z1; vals[2] += z2; vals[3] += z3;
        vals[4] += z0 * z0; vals[5] += z1 * z1; vals[6] += z2 * z2; vals[7] += z3 * z3;
        e = en; d = dn; s = sn; ea = ean;
    }
    float* Rout = g_stats + region * 128;
#pragma unroll
    for (int v = 0; v < 8; v++) {
        __syncthreads();
        rb[slot * 17 + lane] = vals[v];
        __syncthreads();
        if (slot == 0) {
            float tsum = 0.f;
#pragma unroll
            for (int k = 0; k < 16; k++) tsum += rb[k * 17 + lane];
            atomicAdd(&Rout[(v < 4 ? 0 : 64) + lane * 4 + (v & 3)], tsum);
        }
    }
}

// edge pass 2: 64-edge tiles, double-buffered pipeline; fp16-A single + fp16-B split
// (2-term MMA: AhBh + AhBl). x1 = relu(bn1(z1)); z2 = x1 @ W2; store z2 fp16 + stats.
__global__ void __launch_bounds__(256, 2)
k_edge_z2(const int* __restrict__ EI, const float* __restrict__ EA,
          const float* __restrict__ W1, const float* __restrict__ W2,
          const float* __restrict__ g1, const float* __restrict__ be1,
          int regIn, int regOut) {
    __shared__ __align__(16) uint8_t A0h[8192], A1h[8192];
    __shared__ __align__(16) uint8_t Bh[8192], Bl[8192];
    uint32_t A0hS = (uint32_t)__cvta_generic_to_shared(A0h);
    uint32_t A1hS = (uint32_t)__cvta_generic_to_shared(A1h);
    uint32_t BhS = (uint32_t)__cvta_generic_to_shared(Bh);
    uint32_t BlS = (uint32_t)__cvta_generic_to_shared(Bl);
    int tid = threadIdx.x, warp = tid >> 5, lane = tid & 31;
    int mb = warp & 3, nh = warp >> 2;
    int lane16 = tid & 15;
    int g = lane >> 2, t = lane & 3;
    const float invE = 1.0f / (float)NE;
    const float* Rin = g_stats + regIn * 128;
    float* Rout = g_stats + regOut * 128;
    const int NT = NE / 64;

    load_B_split_h(W2, Bh, Bl, tid);
    float sc[4], sh[4];
#pragma unroll
    for (int j = 0; j < 4; j++) bn_coef(Rin, g1, be1, invE, lane16 * 4 + j, sc[j], sh[j]);
    float4 wcv = *(const float4*)(W1 + 128 * 64 + lane16 * 4);

    float localS[8], localQ[8];
#pragma unroll
    for (int i = 0; i < 8; i++) { localS[i] = 0.f; localQ[i] = 0.f; }

    int rbase = tid >> 4;
    float4 pr[4], qr[4];
    float ear[4];

    int tile = blockIdx.x;
    if (tile < NT) {
#pragma unroll
        for (int k = 0; k < 4; k++) {
            size_t e = (size_t)tile * 64 + rbase + k * 16;
            int d = EI[NE + e], s = EI[e];
            ear[k] = EA[e];
            pr[k] = *(const float4*)(g_P + (size_t)d * 64 + lane16 * 4);
            qr[k] = *(const float4*)(g_Q + (size_t)s * 64 + lane16 * 4);
        }
#pragma unroll
        for (int k = 0; k < 4; k++) {
            float4 xv;
            xv.x = fmaxf(fmaf(pr[k].x + qr[k].x + wcv.x * ear[k], sc[0], sh[0]), 0.f);
            xv.y = fmaxf(fmaf(pr[k].y + qr[k].y + wcv.y * ear[k], sc[1], sh[1]), 0.f);
            xv.z = fmaxf(fmaf(pr[k].z + qr[k].z + wcv.z * ear[k], sc[2], sh[2]), 0.f);
            xv.w = fmaxf(fmaf(pr[k].w + qr[k].w + wcv.w * ear[k], sc[3], sh[3]), 0.f);
            storeA4h(A0h, rbase + k * 16, lane16 * 4, xv);
        }
    }
    __syncthreads();

    int pb = 0;
    while (tile < NT) {
        int next = tile + gridDim.x;
        bool nvalid = next < NT;
        if (nvalid) {
#pragma unroll
            for (int k = 0; k < 4; k++) {
                size_t e = (size_t)next * 64 + rbase + k * 16;
                int d = EI[NE + e], s = EI[e];
                ear[k] = EA[e];
                pr[k] = *(const float4*)(g_P + (size_t)d * 64 + lane16 * 4);
                qr[k] = *(const float4*)(g_Q + (size_t)s * 64 + lane16 * 4);
            }
        }
        uint32_t aHS = pb ? A1hS : A0hS;
        float acc[4][4];
#pragma unroll
        for (int i = 0; i < 4; i++) { acc[i][0]=acc[i][1]=acc[i][2]=acc[i][3]=0.f; }
        int ra0 = mb * 16;
#pragma unroll
        for (int kk = 0; kk < 4; kk++) {
            int kb = kk * 32;
            uint32_t ah0, ah1, ah2, ah3;
            ldsm_x4(ah0, ah1, ah2, ah3, ldsm_addr(aHS, ra0, kb, lane));
#pragma unroll
            for (int np = 0; np < 2; np++) {
                uint32_t b00, b01, b10, b11, c00, c01, c10, c11;
                ldsm_x4(b00, b01, b10, b11, ldsm_addr(BhS, nh * 32 + np * 16, kb, lane));
                ldsm_x4(c00, c01, c10, c11, ldsm_addr(BlS, nh * 32 + np * 16, kb, lane));
                mma4h(acc[np * 2], ah0, ah1, ah2, ah3, b00, b10);
                mma4h(acc[np * 2], ah0, ah1, ah2, ah3, c00, c10);
                mma4h(acc[np * 2 + 1], ah0, ah1, ah2, ah3, b01, b11);
                mma4h(acc[np * 2 + 1], ah0, ah1, ah2, ah3, c01, c11);
            }
        }
        size_t r0 = (size_t)tile * 64 + mb * 16 + g;
#pragma unroll
        for (int n0 = 0; n0 < 4; n0++) {
            int c = nh * 32 + n0 * 8 + 2 * t;
            float a0 = acc[n0][0], a1 = acc[n0][1], a2 = acc[n0][2], a3 = acc[n0][3];
            *(__half2*)(g_z2h + r0 * 64 + c) = __floats2half2_rn(a0, a1);
            *(__half2*)(g_z2h + (r0 + 8) * 64 + c) = __floats2half2_rn(a2, a3);
            localS[n0 * 2] += a0 + a2;
            localS[n0 * 2 + 1] += a1 + a3;
            localQ[n0 * 2] += a0 * a0 + a2 * a2;
            localQ[n0 * 2 + 1] += a1 * a1 + a3 * a3;
        }
        if (!nvalid) break;
        __syncthreads();
        uint8_t* nAh = pb ? A0h : A1h;
#pragma unroll
        for (int k = 0; k < 4; k++) {
            float4 xv;
            xv.x = fmaxf(fmaf(pr[k].x + qr[k].x + wcv.x * ear[k], sc[0], sh[0]), 0.f);
            xv.y = fmaxf(fmaf(pr[k].y + qr[k].y + wcv.y * ear[k], sc[1], sh[1]), 0.f);
            xv.z = fmaxf(fmaf(pr[k].z + qr[k].z + wcv.z * ear[k], sc[2], sh[2]), 0.f);
            xv.w = fmaxf(fmaf(pr[k].w + qr[k].w + wcv.w * ear[k], sc[3], sh[3]), 0.f);
            storeA4h(nAh, rbase + k * 16, lane16 * 4, xv);
        }
        __syncthreads();
        tile = next;
        pb ^= 1;
    }
    float* sbuf = (float*)A0h;
    __syncthreads();
    for (int i = tid; i < 128; i += 256) sbuf[i] = 0.f;
    __syncthreads();
#pragma unroll
    for (int n0 = 0; n0 < 4; n0++) {
        int c = nh * 32 + n0 * 8 + 2 * t;
        atomicAdd(sbuf + c, localS[n0 * 2]);
        atomicAdd(sbuf + c + 1, localS[n0 * 2 + 1]);
        atomicAdd(sbuf + 64 + c, localQ[n0 * 2]);
        atomicAdd(sbuf + 64 + c + 1, localQ[n0 * 2 + 1]);
    }
    __syncthreads();
    for (int i = tid; i < 128; i += 256) atomicAdd(Rout + i, sbuf[i]);
}

// edge pass 3: m = relu(bn2(z2_fp16)); fp32 vectorized scatter-add into aggr[dst]
__global__ void k_edge_scatter(const int* __restrict__ EI, const float* __restrict__ g2,
                               const float* __restrict__ be2, int regIn) {
    int tid = threadIdx.x, lane = tid & 15;
    const float invE = 1.0f / (float)NE;
    const float* Rin = g_stats + regIn * 128;
    float4 scv, shv;
    bn_coef(Rin, g2, be2, invE, lane * 4 + 0, scv.x, shv.x);
    bn_coef(Rin, g2, be2, invE, lane * 4 + 1, scv.y, shv.y);
    bn_coef(Rin, g2, be2, invE, lane * 4 + 2, scv.z, shv.z);
    bn_coef(Rin, g2, be2, invE, lane * 4 + 3, scv.w, shv.w);
    size_t stride = (size_t)gridDim.x * blockDim.x;
    for (size_t i = (size_t)blockIdx.x * blockDim.x + tid; i < (size_t)NE * 16; i += stride) {
        size_t e = i >> 4;
        uint2 zu = *(const uint2*)(g_z2h + e * 64 + lane * 4);
        float2 z01 = __half22float2(*(__half2*)&zu.x);
        float2 z23 = __half22float2(*(__half2*)&zu.y);
        float m0 = fmaxf(fmaf(z01.x, scv.x, shv.x), 0.f);
        float m1 = fmaxf(fmaf(z01.y, scv.y, shv.y), 0.f);
        float m2 = fmaxf(fmaf(z23.x, scv.z, shv.z), 0.f);
        float m3 = fmaxf(fmaf(z23.y, scv.w, shv.w), 0.f);
        int d = EI[NE + e];
        float* addr = g_aggr + (size_t)d * 64 + lane * 4;
        asm volatile("red.global.add.v4.f32 [%0], {%1,%2,%3,%4};"
                     :: "l"(addr), "f"(m0), "f"(m1), "f"(m2), "f"(m3) : "memory");
    }
}

// z3 = h @ U1[:64] + aggr @ U1[64:128]; store zn + stats(z3)
__global__ void k_node_z3(const float* __restrict__ U1, int regOut) {
    DECL_SMEM
    int tid = threadIdx.x, warp = tid >> 5, lane = tid & 31;
    int row0 = blockIdx.x * 128;
    float* Rout = g_stats + regOut * 128;

    for (int i = tid; i < 2048; i += 256) {
        int r = i >> 4, c4 = (i & 15) * 4, gr = row0 + r;
        float4 v = make_float4(0, 0, 0, 0);
        if (gr < NN) v = *(const float4*)(g_h + (size_t)gr * 64 + c4);
        splitA4(Ah, Al, r, c4, v);
    }
    load_B_split(U1, Bh, Bl, tid);
    __syncthreads();
    float acc[8][4];
#pragma unroll
    for (int i = 0; i < 8; i++) { acc[i][0]=acc[i][1]=acc[i][2]=acc[i][3]=0.f; }
    mma_block(AhS, AlS, BhS, BlS, acc, warp, lane);
    __syncthreads();
    for (int i = tid; i < 2048; i += 256) {
        int r = i >> 4, c4 = (i & 15) * 4, gr = row0 + r;
        float4 v = make_float4(0, 0, 0, 0);
        if (gr < NN) v = *(const float4*)(g_aggr + (size_t)gr * 64 + c4);
        splitA4(Ah, Al, r, c4, v);
    }
    load_B_split(U1 + 4096, Bh, Bl, tid);
    __syncthreads();
    mma_block(AhS, AlS, BhS, BlS, acc, warp, lane);

    int g = lane >> 2, t = lane & 3;
    int r0 = row0 + warp * 16 + g;
    float localS[16], localQ[16];
#pragma unroll
    for (int i = 0; i < 16; i++) { localS[i] = 0.f; localQ[i] = 0.f; }
#pragma unroll
    for (int n0 = 0; n0 < 8; n0++) {
        int c = n0 * 8 + 2 * t;
        float a0 = acc[n0][0], a1 = acc[n0][1], a2 = acc[n0][2], a3 = acc[n0][3];
        if (r0 < NN) *(float2*)(g_zn + (size_t)r0 * 64 + c) = make_float2(a0, a1);
        if (r0 + 8 < NN) *(float2*)(g_zn + (size_t)(r0 + 8) * 64 + c) = make_float2(a2, a3);
        localS[n0 * 2] += a0 + a2;
        localS[n0 * 2 + 1] += a1 + a3;
        localQ[n0 * 2] += a0 * a0 + a2 * a2;
        localQ[n0 * 2 + 1] += a1 * a1 + a3 * a3;
    }
    stats_reduce_store((float*)Ah, localS, localQ, lane, tid, Rout);
}

// z4 = relu(bn3(zn)) @ U2; store zn2 + stats(z4)
__global__ void k_node_z4(const float* __restrict__ U2, const float* __restrict__ g3,
                          const float* __restrict__ be3, int regIn, int regOut) {
    DECL_SMEM
    int tid = threadIdx.x, warp = tid >> 5, lane = tid & 31;
    int row0 = blockIdx.x * 128;
    const float invN = 1.0f / (float)NN;
    const float* Rin = g_stats + regIn * 128;
    float* Rout = g_stats + regOut * 128;

    for (int i = tid; i < 2048; i += 256) {
        int r = i >> 4, c4 = (i & 15) * 4, gr = row0 + r;
        float4 v = make_float4(0, 0, 0, 0);
        if (gr < NN) {
            float4 z = *(const float4*)(g_zn + (size_t)gr * 64 + c4);
            float sc, sh;
            bn_coef(Rin, g3, be3, invN, c4 + 0, sc, sh); v.x = fmaxf(fmaf(z.x, sc, sh), 0.f);
            bn_coef(Rin, g3, be3, invN, c4 + 1, sc, sh); v.y = fmaxf(fmaf(z.y, sc, sh), 0.f);
            bn_coef(Rin, g3, be3, invN, c4 + 2, sc, sh); v.z = fmaxf(fmaf(z.z, sc, sh), 0.f);
            bn_coef(Rin, g3, be3, invN, c4 + 3, sc, sh); v.w = fmaxf(fmaf(z.w, sc, sh), 0.f);
        }
        splitA4(Ah, Al, r, c4, v);
    }
    load_B_split(U2, Bh, Bl, tid);
    __syncthreads();
    float acc[8][4];
#pragma unroll
    for (int i = 0; i < 8; i++) { acc[i][0]=acc[i][1]=acc[i][2]=acc[i][3]=0.f; }
    mma_block(AhS, AlS, BhS, BlS, acc, warp, lane);

    int g = lane >> 2, t = lane & 3;
    int r0 = row0 + warp * 16 + g;
    float localS[16], localQ[16];
#pragma unroll
    for (int i = 0; i < 16; i++) { localS[i] = 0.f; localQ[i] = 0.f; }
#pragma unroll
    for (int n0 = 0; n0 < 8; n0++) {
        int c = n0 * 8 + 2 * t;
        float a0 = acc[n0][0], a1 = acc[n0][1], a2 = acc[n0][2], a3 = acc[n0][3];
        if (r0 < NN) *(float2*)(g_zn2 + (size_t)r0 * 64 + c) = make_float2(a0, a1);
        if (r0 + 8 < NN) *(float2*)(g_zn2 + (size_t)(r0 + 8) * 64 + c) = make_float2(a2, a3);
        localS[n0 * 2] += a0 + a2;
        localS[n0 * 2 + 1] += a1 + a3;
        localQ[n0 * 2] += a0 * a0 + a2 * a2;
        localQ[n0 * 2 + 1] += a1 * a1 + a3 * a3;
    }
    stats_reduce_store((float*)Ah, localS, localQ, lane, tid, Rout);
}

// out[n] = (h[n] + relu(bn4(zn2[n]))) . pred_W + pred_b
__global__ void k_pred(const float* __restrict__ Wp, const float* __restrict__ bp,
                       const float* __restrict__ g4, const float* __restrict__ be4,
                       int regIn, float* __restrict__ out) {
    __shared__ float Wps[64];
    int tid = threadIdx.x;
    if (tid < 64) Wps[tid] = Wp[tid];
    __syncthreads();
    const float invN = 1.0f / (float)NN;
    const float* Rin = g_stats + regIn * 128;
    int lane = tid & 31, w = tid >> 5;
    int c = lane * 2;
    float sc0, sh0, sc1, sh1;
    bn_coef(Rin, g4, be4, invN, c, sc0, sh0);
    bn_coef(Rin, g4, be4, invN, c + 1, sc1, sh1);
    int n = blockIdx.x * 8 + w;
    if (n >= NN) return;
    float2 hv = *(const float2*)(g_h + (size_t)n * 64 + c);
    float2 zv = *(const float2*)(g_zn2 + (size_t)n * 64 + c);
    float v0 = hv.x + fmaxf(fmaf(zv.x, sc0, sh0), 0.f);
    float v1 = hv.y + fmaxf(fmaf(zv.y, sc1, sh1), 0.f);
    float p = v0 * Wps[c] + v1 * Wps[c + 1];
#pragma unroll
    for (int off = 16; off; off >>= 1) p += __shfl_xor_sync(0xffffffffu, p, off);
    if (lane == 0) out[n] = p + bp[0];
}

// ---------------- launch ----------------
extern "C" void kernel_launch(void* const* d_in, const int* in_sizes, int n_in,
                              void* d_out, int out_size) {
    const float* x    = (const float*)d_in[0];
    const int*   EI   = (const int*)d_in[1];
    const float* EA   = (const float*)d_in[2];
    const float* linW = (const float*)d_in[3];
    const float* linb = (const float*)d_in[4];
    const float* mW1  = (const float*)d_in[5];
    const float* mg1  = (const float*)d_in[7];
    const float* mbe1 = (const float*)d_in[8];
    const float* mW2  = (const float*)d_in[9];
    const float* mg2  = (const float*)d_in[11];
    const float* mbe2 = (const float*)d_in[12];
    const float* uW1  = (const float*)d_in[13];
    const float* ug1  = (const float*)d_in[15];
    const float* ube1 = (const float*)d_in[16];
    const float* uW2  = (const float*)d_in[17];
    const float* ug2  = (const float*)d_in[19];
    const float* ube2 = (const float*)d_in[20];
    const float* pW   = (const float*)d_in[21];
    const float* pb   = (const float*)d_in[22];
    float* out = (float*)d_out;

    const int NODE_TILES = (NN + 127) / 128;  // 391

    k_lin_in<<<1184, 256>>>(x, linW, linb);
    for (int l = 0; l < NLAYER; l++) {
        const float* W1 = mW1 + (size_t)l * 129 * 64;
        const float* W2 = mW2 + (size_t)l * 64 * 64;
        const float* U1 = uW1 + (size_t)l * 128 * 64;
        const float* U2 = uW2 + (size_t)l * 64 * 64;
        int R = l * 4;
        k_node_PQ<<<NODE_TILES, 256>>>(
            W1, l ? ug2 + (l - 1) * 64 : (const float*)nullptr,
            l ? ube2 + (l - 1) * 64 : (const float*)nullptr,
            l ? (l - 1) * 4 + 3 : 0, l ? 1 : 0);
        k_edge_z1_stats<<<1480, 256>>>(EI, EA, W1, R + 0);
        k_edge_z2<<<296, 256>>>(EI, EA, W1, W2, mg1 + l * 64, mbe1 + l * 64, R + 0, R + 1);
        k_edge_scatter<<<9472, 256>>>(EI, mg2 + l * 64, mbe2 + l * 64, R + 1);
        k_node_z3<<<NODE_TILES, 256>>>(U1, R + 2);
        k_node_z4<<<NODE_TILES, 256>>>(U2, ug1 + l * 64, ube1 + l * 64, R + 2, R + 3);
    }
    k_pred<<<(NN + 7) / 8, 256>>>(pW, pb, ug2 + 3 * 64, ube2 + 3 * 64, 15, out);
    (void)in_sizes; (void)n_in; (void)out_size;
}

// round 16
// speedup vs baseline: 1.4398x; 1.4398x over previous
#include <cuda_runtime.h>
#include <cuda_bf16.h>
#include <cuda_fp16.h>
#include <cstdint>

#define NN 50000
#define NE 1600000
#define NLAYER 4
#define BN_EPS 1e-5f

// ---------------- scratch (device globals) ----------------
__device__ __align__(16) float g_h[NN * 64];
__device__ __align__(16) float g_P[NN * 64];
__device__ __align__(16) float g_Q[NN * 64];
__device__ __align__(16) float g_aggr[NN * 64];
__device__ __align__(16) float g_zn[NN * 64];
__device__ __align__(16) float g_zn2[NN * 64];
__device__ __align__(16) __half g_z2h[(size_t)NE * 64];   // fp16 z2 edge scratch
__device__ __align__(16) float g_stats[2048];

__device__ __forceinline__ int swz(int r, int kb) {
    return r * 128 + (kb ^ ((r & 7) << 4));
}

// ---------------- helpers ----------------
__device__ __forceinline__ void bn_coef(const float* __restrict__ R,
                                        const float* __restrict__ gam,
                                        const float* __restrict__ bet,
                                        float invCnt, int c, float& sc, float& sh) {
    float mu = R[c] * invCnt;
    float var = R[64 + c] * invCnt - mu * mu;
    sc = gam[c] * rsqrtf(var + BN_EPS);
    sh = bet[c] - mu * sc;
}

__device__ __forceinline__ void mma4(float c[4], uint32_t a0, uint32_t a1, uint32_t a2,
                                     uint32_t a3, uint32_t b0, uint32_t b1) {
    asm volatile(
        "mma.sync.aligned.m16n8k16.row.col.f32.bf16.bf16.f32 "
        "{%0,%1,%2,%3}, {%4,%5,%6,%7}, {%8,%9}, {%0,%1,%2,%3};\n"
        : "+f"(c[0]), "+f"(c[1]), "+f"(c[2]), "+f"(c[3])
        : "r"(a0), "r"(a1), "r"(a2), "r"(a3), "r"(b0), "r"(b1));
}

__device__ __forceinline__ void mma4h(float c[4], uint32_t a0, uint32_t a1, uint32_t a2,
                                      uint32_t a3, uint32_t b0, uint32_t b1) {
    asm volatile(
        "mma.sync.aligned.m16n8k16.row.col.f32.f16.f16.f32 "
        "{%0,%1,%2,%3}, {%4,%5,%6,%7}, {%8,%9}, {%0,%1,%2,%3};\n"
        : "+f"(c[0]), "+f"(c[1]), "+f"(c[2]), "+f"(c[3])
        : "r"(a0), "r"(a1), "r"(a2), "r"(a3), "r"(b0), "r"(b1));
}

__device__ __forceinline__ void ldsm_x4(uint32_t& r0, uint32_t& r1, uint32_t& r2,
                                        uint32_t& r3, uint32_t addr) {
    asm volatile("ldmatrix.sync.aligned.m8n8.x4.shared.b16 {%0,%1,%2,%3}, [%4];"
                 : "=r"(r0), "=r"(r1), "=r"(r2), "=r"(r3) : "r"(addr));
}

__device__ __forceinline__ uint32_t ldsm_addr(uint32_t base, int row0, int kb, int lane) {
    int row = row0 + (lane & 15);
    int kbb = kb + (lane & 16);
    return base + row * 128 + (kbb ^ ((row & 7) << 4));
}

// C[128x64] += A[128x64] @ B[64x64]; 8 warps each m16 x n64. bf16 3-term split (node side).
__device__ __forceinline__ void mma_block(uint32_t AhS, uint32_t AlS,
                                          uint32_t BhS, uint32_t BlS,
                                          float acc[8][4], int warp, int lane) {
    int ra0 = warp * 16;
#pragma unroll
    for (int kk = 0; kk < 4; kk++) {
        int kb = kk * 32;
        uint32_t ah0, ah1, ah2, ah3, al0, al1, al2, al3;
        ldsm_x4(ah0, ah1, ah2, ah3, ldsm_addr(AhS, ra0, kb, lane));
        ldsm_x4(al0, al1, al2, al3, ldsm_addr(AlS, ra0, kb, lane));
#pragma unroll
        for (int np = 0; np < 4; np++) {
            uint32_t b00, b01, b10, b11, c00, c01, c10, c11;
            ldsm_x4(b00, b01, b10, b11, ldsm_addr(BhS, np * 16, kb, lane));
            ldsm_x4(c00, c01, c10, c11, ldsm_addr(BlS, np * 16, kb, lane));
            mma4(acc[np * 2], ah0, ah1, ah2, ah3, b00, b10);
            mma4(acc[np * 2], ah0, ah1, ah2, ah3, c00, c10);
            mma4(acc[np * 2], al0, al1, al2, al3, b00, b10);
            mma4(acc[np * 2 + 1], ah0, ah1, ah2, ah3, b01, b11);
            mma4(acc[np * 2 + 1], ah0, ah1, ah2, ah3, c01, c11);
            mma4(acc[np * 2 + 1], al0, al1, al2, al3, b01, b11);
        }
    }
}

// bf16 weight split (node side)
__device__ __forceinline__ void load_B_split(const float* __restrict__ W,
                                             uint8_t* Bh, uint8_t* Bl, int tid) {
    for (int i = tid; i < 4096; i += 256) {
        int k = i >> 6, n = i & 63;
        float w = W[i];
        __nv_bfloat16 hh = __float2bfloat16(w);
        int o = swz(n, 2 * k);
        *(__nv_bfloat16*)(Bh + o) = hh;
        *(__nv_bfloat16*)(Bl + o) = __float2bfloat16(w - __bfloat162float(hh));
    }
}

// fp16 weight split (edge z2)
__device__ __forceinline__ void load_B_split_h(const float* __restrict__ W,
                                               uint8_t* Bh, uint8_t* Bl, int tid) {
    for (int i = tid; i < 4096; i += 256) {
        int k = i >> 6, n = i & 63;
        float w = W[i];
        __half hh = __float2half_rn(w);
        int o = swz(n, 2 * k);
        *(__half*)(Bh + o) = hh;
        *(__half*)(Bl + o) = __float2half_rn(w - __half2float(hh));
    }
}

// bf16 hi/lo A split-store (node side)
__device__ __forceinline__ void splitA4(uint8_t* Ah, uint8_t* Al, int r, int c4, float4 v) {
    int o = swz(r, 2 * c4);
    float2 p0 = make_float2(v.x, v.y), p1 = make_float2(v.z, v.w);
    __nv_bfloat162 h0 = __float22bfloat162_rn(p0);
    __nv_bfloat162 h1 = __float22bfloat162_rn(p1);
    uint2 hv;
    hv.x = *(uint32_t*)&h0; hv.y = *(uint32_t*)&h1;
    *(uint2*)(Ah + o) = hv;
    float2 r0 = make_float2(p0.x - __low2float(h0), p0.y - __high2float(h0));
    float2 r1 = make_float2(p1.x - __low2float(h1), p1.y - __high2float(h1));
    __nv_bfloat162 l0 = __float22bfloat162_rn(r0);
    __nv_bfloat162 l1 = __float22bfloat162_rn(r1);
    uint2 lv;
    lv.x = *(uint32_t*)&l0; lv.y = *(uint32_t*)&l1;
    *(uint2*)(Al + o) = lv;
}

// fp16 A store (edge z2)
__device__ __forceinline__ void storeA4h(uint8_t* Ah, int r, int c4, float4 v) {
    int o = swz(r, 2 * c4);
    __half2 h0 = __floats2half2_rn(v.x, v.y);
    __half2 h1 = __floats2half2_rn(v.z, v.w);
    uint2 hv;
    hv.x = *(uint32_t*)&h0; hv.y = *(uint32_t*)&h1;
    *(uint2*)(Ah + o) = hv;
}

__device__ __forceinline__ void stats_reduce_store(float* sbuf, const float localS[16],
                                                   const float localQ[16], int lane, int tid,
                                                   float* __restrict__ Rout) {
    __syncthreads();
    for (int i = tid; i < 128; i += 256) sbuf[i] = 0.f;
    __syncthreads();
    int t = lane & 3;
#pragma unroll
    for (int n0 = 0; n0 < 8; n0++) {
        atomicAdd(sbuf + n0 * 8 + 2 * t, localS[n0 * 2]);
        atomicAdd(sbuf + n0 * 8 + 2 * t + 1, localS[n0 * 2 + 1]);
        atomicAdd(sbuf + 64 + n0 * 8 + 2 * t, localQ[n0 * 2]);
        atomicAdd(sbuf + 64 + n0 * 8 + 2 * t + 1, localQ[n0 * 2 + 1]);
    }
    __syncthreads();
    for (int i = tid; i < 128; i += 256) atomicAdd(Rout + i, sbuf[i]);
}

#define DECL_SMEM                                              \
    __shared__ __align__(16) uint8_t Ah[16384], Al[16384];     \
    __shared__ __align__(16) uint8_t Bh[8192], Bl[8192];       \
    uint32_t AhS = (uint32_t)__cvta_generic_to_shared(Ah);     \
    uint32_t AlS = (uint32_t)__cvta_generic_to_shared(Al);     \
    uint32_t BhS = (uint32_t)__cvta_generic_to_shared(Bh);     \
    uint32_t BlS = (uint32_t)__cvta_generic_to_shared(Bl);

// ---------------- kernels ----------------

__global__ void k_lin_in(const float* __restrict__ x, const float* __restrict__ W,
                         const float* __restrict__ b) {
    __shared__ __align__(16) float Ws[6 * 64];
    __shared__ float bs[64];
    int tid = threadIdx.x;
    for (int i = tid; i < 384; i += 256) Ws[i] = W[i];
    if (tid < 64) bs[tid] = b[tid];
    if (blockIdx.x == 0)
        for (int i = tid; i < 2048; i += 256) g_stats[i] = 0.f;
    __syncthreads();
    int c = tid & 63;
    for (int n = blockIdx.x * 4 + (tid >> 6); n < NN; n += gridDim.x * 4) {
        float acc = bs[c];
#pragma unroll
        for (int k = 0; k < 6; k++) acc = fmaf(x[n * 6 + k], Ws[k * 64 + c], acc);
        g_h[n * 64 + c] = acc;
    }
}

// (h += relu(bn4_{l-1}(zn2)) fused when doUpd); P = h@W1[:64]; Q = h@W1[64:128]; zero aggr
__global__ void k_node_PQ(const float* __restrict__ W1, const float* __restrict__ gam,
                          const float* __restrict__ bet, int prevRegion, int doUpd) {
    DECL_SMEM
    int tid = threadIdx.x, warp = tid >> 5, lane = tid & 31;
    int row0 = blockIdx.x * 128;
    const float* Rp = g_stats + prevRegion * 128;
    const float invN = 1.0f / (float)NN;

    for (int i = tid; i < 2048; i += 256) {
        int r = i >> 4;
        int c4 = (i & 15) * 4;
        int gr = row0 + r;
        float4 v = make_float4(0, 0, 0, 0);
        if (gr < NN) {
            size_t idx = (size_t)gr * 64 + c4;
            v = *(const float4*)(g_h + idx);
            if (doUpd) {
                float4 z = *(const float4*)(g_zn2 + idx);
                float sc, sh;
                bn_coef(Rp, gam, bet, invN, c4 + 0, sc, sh); v.x += fmaxf(fmaf(z.x, sc, sh), 0.f);
                bn_coef(Rp, gam, bet, invN, c4 + 1, sc, sh); v.y += fmaxf(fmaf(z.y, sc, sh), 0.f);
                bn_coef(Rp, gam, bet, invN, c4 + 2, sc, sh); v.z += fmaxf(fmaf(z.z, sc, sh), 0.f);
                bn_coef(Rp, gam, bet, invN, c4 + 3, sc, sh); v.w += fmaxf(fmaf(z.w, sc, sh), 0.f);
                *(float4*)(g_h + idx) = v;
            }
            *(float4*)(g_aggr + idx) = make_float4(0, 0, 0, 0);
        }
        splitA4(Ah, Al, r, c4, v);
    }
    load_B_split(W1, Bh, Bl, tid);
    __syncthreads();

    int g = lane >> 2, t = lane & 3;
    int r0 = row0 + warp * 16 + g;
    {
        float acc[8][4];
#pragma unroll
        for (int i = 0; i < 8; i++) { acc[i][0]=acc[i][1]=acc[i][2]=acc[i][3]=0.f; }
        mma_block(AhS, AlS, BhS, BlS, acc, warp, lane);
#pragma unroll
        for (int n0 = 0; n0 < 8; n0++) {
            int c = n0 * 8 + 2 * t;
            if (r0 < NN) *(float2*)(g_P + (size_t)r0 * 64 + c) = make_float2(acc[n0][0], acc[n0][1]);
            if (r0 + 8 < NN) *(float2*)(g_P + (size_t)(r0 + 8) * 64 + c) = make_float2(acc[n0][2], acc[n0][3]);
        }
    }
    __syncthreads();
    load_B_split(W1 + 4096, Bh, Bl, tid);
    __syncthreads();
    {
        float acc[8][4];
#pragma unroll
        for (int i = 0; i < 8; i++) { acc[i][0]=acc[i][1]=acc[i][2]=acc[i][3]=0.f; }
        mma_block(AhS, AlS, BhS, BlS, acc, warp, lane);
#pragma unroll
        for (int n0 = 0; n0 < 8; n0++) {
            int c = n0 * 8 + 2 * t;
            if (r0 < NN) *(float2*)(g_Q + (size_t)r0 * 64 + c) = make_float2(acc[n0][0], acc[n0][1]);
            if (r0 + 8 < NN) *(float2*)(g_Q + (size_t)(r0 + 8) * 64 + c) = make_float2(acc[n0][2], acc[n0][3]);
        }
    }
}

// edge pass 1: z1 = P[dst]+Q[src]+w1c*ea -> col sums/sumsqs (index loads pipelined)
__global__ void k_edge_z1_stats(const int* __restrict__ EI, const float* __restrict__ EA,
                                const float* __restrict__ W1, int region) {
    __shared__ __align__(16) float wc[64];
    __shared__ float rb[16 * 17];
    int tid = threadIdx.x, lane = tid & 15, slot = tid >> 4;
    if (tid < 64) wc[tid] = W1[128 * 64 + tid];
    __syncthreads();
    float4 wcv = *(const float4*)(wc + lane * 4);
    float vals[8] = {0, 0, 0, 0, 0, 0, 0, 0};
    int stride = gridDim.x * 16;
    int e = blockIdx.x * 16 + slot;
    int d = 0, s = 0;
    float ea = 0.f;
    if (e < NE) { d = EI[NE + e]; s = EI[e]; ea = EA[e]; }
    while (e < NE) {
        int en = e + stride;
        int dn = 0, sn = 0;
        float ean = 0.f;
        if (en < NE) { dn = EI[NE + en]; sn = EI[en]; ean = EA[en]; }
        float4 p = *(const float4*)(g_P + (size_t)d * 64 + lane * 4);
        float4 q = *(const float4*)(g_Q + (size_t)s * 64 + lane * 4);
        float z0 = p.x + q.x + wcv.x * ea;
        float z1 = p.y + q.y + wcv.y * ea;
        float z2 = p.z + q.z + wcv.z * ea;
        float z3 = p.w + q.w + wcv.w * ea;
        vals[0] += z0; vals[1] += z1; vals[2] += z2; vals[3] += z3;
        vals[4] += z0 * z0; vals[5] += z1 * z1; vals[6] += z2 * z2; vals[7] += z3 * z3;
        e = en; d = dn; s = sn; ea = ean;
    }
    float* Rout = g_stats + region * 128;
#pragma unroll
    for (int v = 0; v < 8; v++) {
        __syncthreads();
        rb[slot * 17 + lane] = vals[v];
        __syncthreads();
        if (slot == 0) {
            float tsum = 0.f;
#pragma unroll
            for (int k = 0; k < 16; k++) tsum += rb[k * 17 + lane];
            atomicAdd(&Rout[(v < 4 ? 0 : 64) + lane * 4 + (v & 3)], tsum);
        }
    }
}

// edge pass 2: 64-edge tiles, double-buffered pipeline; fp16-A single + fp16-B split
// (2-term MMA: AhBh + AhBl). x1 = relu(bn1(z1)); z2 = x1 @ W2; store z2 fp16 + stats.
__global__ void __launch_bounds__(256, 2)
k_edge_z2(const int* __restrict__ EI, const float* __restrict__ EA,
          const float* __restrict__ W1, const float* __restrict__ W2,
          const float* __restrict__ g1, const float* __restrict__ be1,
          int regIn, int regOut) {
    __shared__ __align__(16) uint8_t A0h[8192], A1h[8192];
    __shared__ __align__(16) uint8_t Bh[8192], Bl[8192];
    uint32_t A0hS = (uint32_t)__cvta_generic_to_shared(A0h);
    uint32_t A1hS = (uint32_t)__cvta_generic_to_shared(A1h);
    uint32_t BhS = (uint32_t)__cvta_generic_to_shared(Bh);
    uint32_t BlS = (uint32_t)__cvta_generic_to_shared(Bl);
    int tid = threadIdx.x, warp = tid >> 5, lane = tid & 31;
    int mb = warp & 3, nh = warp >> 2;
    int lane16 = tid & 15;
    int g = lane >> 2, t = lane & 3;
    const float invE = 1.0f / (float)NE;
    const float* Rin = g_stats + regIn * 128;
    float* Rout = g_stats + regOut * 128;
    const int NT = NE / 64;

    load_B_split_h(W2, Bh, Bl, tid);
    float sc[4], sh[4];
#pragma unroll
    for (int j = 0; j < 4; j++) bn_coef(Rin, g1, be1, invE, lane16 * 4 + j, sc[j], sh[j]);
    float4 wcv = *(const float4*)(W1 + 128 * 64 + lane16 * 4);

    float localS[8], localQ[8];
#pragma unroll
    for (int i = 0; i < 8; i++) { localS[i] = 0.f; localQ[i] = 0.f; }

    int rbase = tid >> 4;
    float4 pr[4], qr[4];
    float ear[4];

    int tile = blockIdx.x;
    if (tile < NT) {
#pragma unroll
        for (int k = 0; k < 4; k++) {
            size_t e = (size_t)tile * 64 + rbase + k * 16;
            int d = EI[NE + e], s = EI[e];
            ear[k] = EA[e];
            pr[k] = *(const float4*)(g_P + (size_t)d * 64 + lane16 * 4);
            qr[k] = *(const float4*)(g_Q + (size_t)s * 64 + lane16 * 4);
        }
#pragma unroll
        for (int k = 0; k < 4; k++) {
            float4 xv;
            xv.x = fmaxf(fmaf(pr[k].x + qr[k].x + wcv.x * ear[k], sc[0], sh[0]), 0.f);
            xv.y = fmaxf(fmaf(pr[k].y + qr[k].y + wcv.y * ear[k], sc[1], sh[1]), 0.f);
            xv.z = fmaxf(fmaf(pr[k].z + qr[k].z + wcv.z * ear[k], sc[2], sh[2]), 0.f);
            xv.w = fmaxf(fmaf(pr[k].w + qr[k].w + wcv.w * ear[k], sc[3], sh[3]), 0.f);
            storeA4h(A0h, rbase + k * 16, lane16 * 4, xv);
        }
    }
    __syncthreads();

    int pb = 0;
    while (tile < NT) {
        int next = tile + gridDim.x;
        bool nvalid = next < NT;
        if (nvalid) {
#pragma unroll
            for (int k = 0; k < 4; k++) {
                size_t e = (size_t)next * 64 + rbase + k * 16;
                int d = EI[NE + e], s = EI[e];
                ear[k] = EA[e];
                pr[k] = *(const float4*)(g_P + (size_t)d * 64 + lane16 * 4);
                qr[k] = *(const float4*)(g_Q + (size_t)s * 64 + lane16 * 4);
            }
        }
        uint32_t aHS = pb ? A1hS : A0hS;
        float acc[4][4];
#pragma unroll
        for (int i = 0; i < 4; i++) { acc[i][0]=acc[i][1]=acc[i][2]=acc[i][3]=0.f; }
        int ra0 = mb * 16;
#pragma unroll
        for (int kk = 0; kk < 4; kk++) {
            int kb = kk * 32;
            uint32_t ah0, ah1, ah2, ah3;
            ldsm_x4(ah0, ah1, ah2, ah3, ldsm_addr(aHS, ra0, kb, lane));
#pragma unroll
            for (int np = 0; np < 2; np++) {
                uint32_t b00, b01, b10, b11, c00, c01, c10, c11;
                ldsm_x4(b00, b01, b10, b11, ldsm_addr(BhS, nh * 32 + np * 16, kb, lane));
                ldsm_x4(c00, c01, c10, c11, ldsm_addr(BlS, nh * 32 + np * 16, kb, lane));
                mma4h(acc[np * 2], ah0, ah1, ah2, ah3, b00, b10);
                mma4h(acc[np * 2], ah0, ah1, ah2, ah3, c00, c10);
                mma4h(acc[np * 2 + 1], ah0, ah1, ah2, ah3, b01, b11);
                mma4h(acc[np * 2 + 1], ah0, ah1, ah2, ah3, c01, c11);
            }
        }
        size_t r0 = (size_t)tile * 64 + mb * 16 + g;
#pragma unroll
        for (int n0 = 0; n0 < 4; n0++) {
            int c = nh * 32 + n0 * 8 + 2 * t;
            float a0 = acc[n0][0], a1 = acc[n0][1], a2 = acc[n0][2], a3 = acc[n0][3];
            *(__half2*)(g_z2h + r0 * 64 + c) = __floats2half2_rn(a0, a1);
            *(__half2*)(g_z2h + (r0 + 8) * 64 + c) = __floats2half2_rn(a2, a3);
            localS[n0 * 2] += a0 + a2;
            localS[n0 * 2 + 1] += a1 + a3;
            localQ[n0 * 2] += a0 * a0 + a2 * a2;
            localQ[n0 * 2 + 1] += a1 * a1 + a3 * a3;
        }
        if (!nvalid) break;
        __syncthreads();
        uint8_t* nAh = pb ? A0h : A1h;
#pragma unroll
        for (int k = 0; k < 4; k++) {
            float4 xv;
            xv.x = fmaxf(fmaf(pr[k].x + qr[k].x + wcv.x * ear[k], sc[0], sh[0]), 0.f);
            xv.y = fmaxf(fmaf(pr[k].y + qr[k].y + wcv.y * ear[k], sc[1], sh[1]), 0.f);
            xv.z = fmaxf(fmaf(pr[k].z + qr[k].z + wcv.z * ear[k], sc[2], sh[2]), 0.f);
            xv.w = fmaxf(fmaf(pr[k].w + qr[k].w + wcv.w * ear[k], sc[3], sh[3]), 0.f);
            storeA4h(nAh, rbase + k * 16, lane16 * 4, xv);
        }
        __syncthreads();
        tile = next;
        pb ^= 1;
    }
    float* sbuf = (float*)A0h;
    __syncthreads();
    for (int i = tid; i < 128; i += 256) sbuf[i] = 0.f;
    __syncthreads();
#pragma unroll
    for (int n0 = 0; n0 < 4; n0++) {
        int c = nh * 32 + n0 * 8 + 2 * t;
        atomicAdd(sbuf + c, localS[n0 * 2]);
        atomicAdd(sbuf + c + 1, localS[n0 * 2 + 1]);
        atomicAdd(sbuf + 64 + c, localQ[n0 * 2]);
        atomicAdd(sbuf + 64 + c + 1, localQ[n0 * 2 + 1]);
    }
    __syncthreads();
    for (int i = tid; i < 128; i += 256) atomicAdd(Rout + i, sbuf[i]);
}

// edge pass 3: m = relu(bn2(z2_fp16)); fp32 vectorized scatter-add into aggr[dst]
__global__ void k_edge_scatter(const int* __restrict__ EI, const float* __restrict__ g2,
                               const float* __restrict__ be2, int regIn) {
    int tid = threadIdx.x, lane = tid & 15;
    const float invE = 1.0f / (float)NE;
    const float* Rin = g_stats + regIn * 128;
    float4 scv, shv;
    bn_coef(Rin, g2, be2, invE, lane * 4 + 0, scv.x, shv.x);
    bn_coef(Rin, g2, be2, invE, lane * 4 + 1, scv.y, shv.y);
    bn_coef(Rin, g2, be2, invE, lane * 4 + 2, scv.z, shv.z);
    bn_coef(Rin, g2, be2, invE, lane * 4 + 3, scv.w, shv.w);
    size_t stride = (size_t)gridDim.x * blockDim.x;
    for (size_t i = (size_t)blockIdx.x * blockDim.x + tid; i < (size_t)NE * 16; i += stride) {
        size_t e = i >> 4;
        uint2 zu = *(const uint2*)(g_z2h + e * 64 + lane * 4);
        float2 z01 = __half22float2(*(__half2*)&zu.x);
        float2 z23 = __half22float2(*(__half2*)&zu.y);
        float m0 = fmaxf(fmaf(z01.x, scv.x, shv.x), 0.f);
        float m1 = fmaxf(fmaf(z01.y, scv.y, shv.y), 0.f);
        float m2 = fmaxf(fmaf(z23.x, scv.z, shv.z), 0.f);
        float m3 = fmaxf(fmaf(z23.y, scv.w, shv.w), 0.f);
        int d = EI[NE + e];
        float* addr = g_aggr + (size_t)d * 64 + lane * 4;
        asm volatile("red.global.add.v4.f32 [%0], {%1,%2,%3,%4};"
                     :: "l"(addr), "f"(m0), "f"(m1), "f"(m2), "f"(m3) : "memory");
    }
}

// z3 = h @ U1[:64] + aggr @ U1[64:128]; store zn + stats(z3)
__global__ void k_node_z3(const float* __restrict__ U1, int regOut) {
    DECL_SMEM
    int tid = threadIdx.x, warp = tid >> 5, lane = tid & 31;
    int row0 = blockIdx.x * 128;
    float* Rout = g_stats + regOut * 128;

    for (int i = tid; i < 2048; i += 256) {
        int r = i >> 4, c4 = (i & 15) * 4, gr = row0 + r;
        float4 v = make_float4(0, 0, 0, 0);
        if (gr < NN) v = *(const float4*)(g_h + (size_t)gr * 64 + c4);
        splitA4(Ah, Al, r, c4, v);
    }
    load_B_split(U1, Bh, Bl, tid);
    __syncthreads();
    float acc[8][4];
#pragma unroll
    for (int i = 0; i < 8; i++) { acc[i][0]=acc[i][1]=acc[i][2]=acc[i][3]=0.f; }
    mma_block(AhS, AlS, BhS, BlS, acc, warp, lane);
    __syncthreads();
    for (int i = tid; i < 2048; i += 256) {
        int r = i >> 4, c4 = (i & 15) * 4, gr = row0 + r;
        float4 v = make_float4(0, 0, 0, 0);
        if (gr < NN) v = *(const float4*)(g_aggr + (size_t)gr * 64 + c4);
        splitA4(Ah, Al, r, c4, v);
    }
    load_B_split(U1 + 4096, Bh, Bl, tid);
    __syncthreads();
    mma_block(AhS, AlS, BhS, BlS, acc, warp, lane);

    int g = lane >> 2, t = lane & 3;
    int r0 = row0 + warp * 16 + g;
    float localS[16], localQ[16];
#pragma unroll
    for (int i = 0; i < 16; i++) { localS[i] = 0.f; localQ[i] = 0.f; }
#pragma unroll
    for (int n0 = 0; n0 < 8; n0++) {
        int c = n0 * 8 + 2 * t;
        float a0 = acc[n0][0], a1 = acc[n0][1], a2 = acc[n0][2], a3 = acc[n0][3];
        if (r0 < NN) *(float2*)(g_zn + (size_t)r0 * 64 + c) = make_float2(a0, a1);
        if (r0 + 8 < NN) *(float2*)(g_zn + (size_t)(r0 + 8) * 64 + c) = make_float2(a2, a3);
        localS[n0 * 2] += a0 + a2;
        localS[n0 * 2 + 1] += a1 + a3;
        localQ[n0 * 2] += a0 * a0 + a2 * a2;
        localQ[n0 * 2 + 1] += a1 * a1 + a3 * a3;
    }
    stats_reduce_store((float*)Ah, localS, localQ, lane, tid, Rout);
}

// z4 = relu(bn3(zn)) @ U2; store zn2 + stats(z4)
__global__ void k_node_z4(const float* __restrict__ U2, const float* __restrict__ g3,
                          const float* __restrict__ be3, int regIn, int regOut) {
    DECL_SMEM
    int tid = threadIdx.x, warp = tid >> 5, lane = tid & 31;
    int row0 = blockIdx.x * 128;
    const float invN = 1.0f / (float)NN;
    const float* Rin = g_stats + regIn * 128;
    float* Rout = g_stats + regOut * 128;

    for (int i = tid; i < 2048; i += 256) {
        int r = i >> 4, c4 = (i & 15) * 4, gr = row0 + r;
        float4 v = make_float4(0, 0, 0, 0);
        if (gr < NN) {
            float4 z = *(const float4*)(g_zn + (size_t)gr * 64 + c4);
            float sc, sh;
            bn_coef(Rin, g3, be3, invN, c4 + 0, sc, sh); v.x = fmaxf(fmaf(z.x, sc, sh), 0.f);
            bn_coef(Rin, g3, be3, invN, c4 + 1, sc, sh); v.y = fmaxf(fmaf(z.y, sc, sh), 0.f);
            bn_coef(Rin, g3, be3, invN, c4 + 2, sc, sh); v.z = fmaxf(fmaf(z.z, sc, sh), 0.f);
            bn_coef(Rin, g3, be3, invN, c4 + 3, sc, sh); v.w = fmaxf(fmaf(z.w, sc, sh), 0.f);
        }
        splitA4(Ah, Al, r, c4, v);
    }
    load_B_split(U2, Bh, Bl, tid);
    __syncthreads();
    float acc[8][4];
#pragma unroll
    for (int i = 0; i < 8; i++) { acc[i][0]=acc[i][1]=acc[i][2]=acc[i][3]=0.f; }
    mma_block(AhS, AlS, BhS, BlS, acc, warp, lane);

    int g = lane >> 2, t = lane & 3;
    int r0 = row0 + warp * 16 + g;
    float localS[16], localQ[16];
#pragma unroll
    for (int i = 0; i < 16; i++) { localS[i] = 0.f; localQ[i] = 0.f; }
#pragma unroll
    for (int n0 = 0; n0 < 8; n0++) {
        int c = n0 * 8 + 2 * t;
        float a0 = acc[n0][0], a1 = acc[n0][1], a2 = acc[n0][2], a3 = acc[n0][3];
        if (r0 < NN) *(float2*)(g_zn2 + (size_t)r0 * 64 + c) = make_float2(a0, a1);
        if (r0 + 8 < NN) *(float2*)(g_zn2 + (size_t)(r0 + 8) * 64 + c) = make_float2(a2, a3);
        localS[n0 * 2] += a0 + a2;
        localS[n0 * 2 + 1] += a1 + a3;
        localQ[n0 * 2] += a0 * a0 + a2 * a2;
        localQ[n0 * 2 + 1] += a1 * a1 + a3 * a3;
    }
    stats_reduce_store((float*)Ah, localS, localQ, lane, tid, Rout);
}

// out[n] = (h[n] + relu(bn4(zn2[n]))) . pred_W + pred_b
__global__ void k_pred(const float* __restrict__ Wp, const float* __restrict__ bp,
                       const float* __restrict__ g4, const float* __restrict__ be4,
                       int regIn, float* __restrict__ out) {
    __shared__ float Wps[64];
    int tid = threadIdx.x;
    if (tid < 64) Wps[tid] = Wp[tid];
    __syncthreads();
    const float invN = 1.0f / (float)NN;
    const float* Rin = g_stats + regIn * 128;
    int lane = tid & 31, w = tid >> 5;
    int c = lane * 2;
    float sc0, sh0, sc1, sh1;
    bn_coef(Rin, g4, be4, invN, c, sc0, sh0);
    bn_coef(Rin, g4, be4, invN, c + 1, sc1, sh1);
    int n = blockIdx.x * 8 + w;
    if (n >= NN) return;
    float2 hv = *(const float2*)(g_h + (size_t)n * 64 + c);
    float2 zv = *(const float2*)(g_zn2 + (size_t)n * 64 + c);
    float v0 = hv.x + fmaxf(fmaf(zv.x, sc0, sh0), 0.f);
    float v1 = hv.y + fmaxf(fmaf(zv.y, sc1, sh1), 0.f);
    float p = v0 * Wps[c] + v1 * Wps[c + 1];
#pragma unroll
    for (int off = 16; off; off >>= 1) p += __shfl_xor_sync(0xffffffffu, p, off);
    if (lane == 0) out[n] = p + bp[0];
}

// ---------------- launch ----------------
extern "C" void kernel_launch(void* const* d_in, const int* in_sizes, int n_in,
                              void* d_out, int out_size) {
    const float* x    = (const float*)d_in[0];
    const int*   EI   = (const int*)d_in[1];
    const float* EA   = (const float*)d_in[2];
    const float* linW = (const float*)d_in[3];
    const float* linb = (const float*)d_in[4];
    const float* mW1  = (const float*)d_in[5];
    const float* mg1  = (const float*)d_in[7];
    const float* mbe1 = (const float*)d_in[8];
    const float* mW2  = (const float*)d_in[9];
    const float* mg2  = (const float*)d_in[11];
    const float* mbe2 = (const float*)d_in[12];
    const float* uW1  = (const float*)d_in[13];
    const float* ug1  = (const float*)d_in[15];
    const float* ube1 = (const float*)d_in[16];
    const float* uW2  = (const float*)d_in[17];
    const float* ug2  = (const float*)d_in[19];
    const float* ube2 = (const float*)d_in[20];
    const float* pW   = (const float*)d_in[21];
    const float* pb   = (const float*)d_in[22];
    float* out = (float*)d_out;

    const int NODE_TILES = (NN + 127) / 128;  // 391

    k_lin_in<<<1184, 256>>>(x, linW, linb);
    for (int l = 0; l < NLAYER; l++) {
        const float* W1 = mW1 + (size_t)l * 129 * 64;
        const float* W2 = mW2 + (size_t)l * 64 * 64;
        const float* U1 = uW1 + (size_t)l * 128 * 64;
        const float* U2 = uW2 + (size_t)l * 64 * 64;
        int R = l * 4;
        k_node_PQ<<<NODE_TILES, 256>>>(
            W1, l ? ug2 + (l - 1) * 64 : (const float*)nullptr,
            l ? ube2 + (l - 1) * 64 : (const float*)nullptr,
            l ? (l - 1) * 4 + 3 : 0, l ? 1 : 0);
        k_edge_z1_stats<<<2220, 256>>>(EI, EA, W1, R + 0);
        k_edge_z2<<<888, 256>>>(EI, EA, W1, W2, mg1 + l * 64, mbe1 + l * 64, R + 0, R + 1);
        k_edge_scatter<<<9472, 256>>>(EI, mg2 + l * 64, mbe2 + l * 64, R + 1);
        k_node_z3<<<NODE_TILES, 256>>>(U1, R + 2);
        k_node_z4<<<NODE_TILES, 256>>>(U2, ug1 + l * 64, ube1 + l * 64, R + 2, R + 3);
    }
    k_pred<<<(NN + 7) / 8, 256>>>(pW, pb, ug2 + 3 * 64, ube2 + 3 * 64, 15, out);
    (void)in_sizes; (void)n_in; (void)out_size;
}